// round 7
// baseline (speedup 1.0000x reference)
#include <cuda_runtime.h>
#include <cstdint>
#include <math.h>

#define T_STEPS 2048
#define BATCH   512
#define DIM     128
#define HID     128
#define NG      32          // 4 gates * 8 wires
// smem: Xs(128*132) | Ws(32*128) | bs(32)   (~84.1 KB -> 2 blocks/SM)
#define GEMM_SMEM_FLOATS (128 * 132 + 32 * 128 + 32)
#define GEMM_SMEM_BYTES  (GEMM_SMEM_FLOATS * 4)

__device__ float g_Z[(size_t)T_STEPS * BATCH * NG];   // pre-activations
__device__ float g_A[(size_t)T_STEPS * BATCH * NG];   // poly coeffs [row][gate][8]
__device__ float g_S[(size_t)(T_STEPS + 1) * BATCH];  // compact h chain + final c
__device__ float g_whsum[NG];
__device__ float g_PC[4][8][4];   // [jj][w][g] coeff of cos(z_w) in a_{2jj}
__device__ float g_PS[4][8][4];   // [jj][w][g] coeff of sin(z_w) in a_{2jj+1}

typedef unsigned long long u64;

__device__ __forceinline__ float tanh_fast(float x) {
    float r; asm("tanh.approx.f32 %0, %1;" : "=f"(r) : "f"(x)); return r;
}
__device__ __forceinline__ u64 ffma2(u64 a, u64 b, u64 c) {
    u64 d; asm("fma.rn.f32x2 %0, %1, %2, %3;" : "=l"(d) : "l"(a), "l"(b), "l"(c));
    return d;
}

// ---------------- init: whsum + Lagrange-on-Chebyshev coefficient tables ----------------
__global__ void init_kernel(const float* __restrict__ Wf, const float* __restrict__ Wi,
                            const float* __restrict__ Wu, const float* __restrict__ Wo) {
    __shared__ double sL[8][8];
    const int n = threadIdx.x;         // 0..31
    const int g = n >> 3, w = n & 7;
    const float* W = (g == 0) ? Wf : (g == 1) ? Wi : (g == 2) ? Wu : Wo;
    float s = 0.f;
#pragma unroll
    for (int k = 0; k < 128; k++) s += W[w * 256 + 128 + k];
    g_whsum[n] = s;

    double xk[8];
#pragma unroll
    for (int k = 0; k < 8; k++) xk[k] = 0.75 * cos((2.0 * k + 1.0) * M_PI / 16.0);

    if (n < 8) {   // Lagrange basis L_n -> monomial coeffs (double)
        double cf[8];
        for (int i = 0; i < 8; i++) cf[i] = 0.0;
        cf[0] = 1.0;
        double den = 1.0;
        int deg = 0;
        for (int j = 0; j < 8; j++) {
            if (j == n) continue;
            for (int i = deg + 1; i >= 1; i--) cf[i] = cf[i - 1] - xk[j] * cf[i];
            cf[0] = -xk[j] * cf[0];
            deg++;
            den *= (xk[n] - xk[j]);
        }
        for (int j = 0; j < 8; j++) sL[n][j] = cf[j] / den;
    }
    __syncthreads();

    const double m = (g == 2) ? (1.0 / 16.0) : (1.0 / 32.0);
    for (int jj = 0; jj < 4; jj++) {
        double pc = 0.0, ps = 0.0;
        for (int k = 0; k < 8; k++) {
            double th = (double)s * xk[k];
            pc += sL[k][2 * jj]     * cos(th);
            ps += sL[k][2 * jj + 1] * sin(th);
        }
        g_PC[jj][w][g] = (float)(-m * pc);
        g_PS[jj][w][g] = (float)( m * ps);
    }
}

// ---------------- GEMM: Z[m][n] = sum_k X[m][k] * W_n[k] + b_n ----------------
// R3 framing (single tile/block, 2 blocks/SM) + 2m x 8n thread blocking:
// thread (warp wq, lane): gate g = wq&3 (cols g*8..g*8+7), rows lane+64*(wq>>2) and +32.
// Crossbar: 2 strided A LDS.128 + 8 broadcast B LDS.128 per 4-k chunk = 4096 cyc/tile,
// balanced against the 4096-cyc ffma2 floor.
__global__ void __launch_bounds__(256, 2) gemm_kernel(
    const float* __restrict__ X,
    const float* __restrict__ Wf, const float* __restrict__ bf,
    const float* __restrict__ Wi, const float* __restrict__ bi,
    const float* __restrict__ Wu, const float* __restrict__ bu,
    const float* __restrict__ Wo, const float* __restrict__ bo) {
    extern __shared__ float sm[];
    float* Xs = sm;                    // [128][132]
    float* Ws = sm + 128 * 132;        // [32][128]
    float* bs = Ws + 32 * 128;         // [32]
    const int tid = threadIdx.x;
    const size_t m0 = (size_t)blockIdx.x * 128;

#pragma unroll
    for (int i = 0; i < 16; i++) {
        int idx = tid + i * 256;
        int n = idx >> 7, k = idx & 127;
        int gg = n >> 3, w = n & 7;
        const float* W = (gg == 0) ? Wf : (gg == 1) ? Wi : (gg == 2) ? Wu : Wo;
        Ws[n * 128 + k] = W[w * 256 + k];
    }
    if (tid < 32) {
        int gg = tid >> 3, w = tid & 7;
        const float* bb = (gg == 0) ? bf : (gg == 1) ? bi : (gg == 2) ? bu : bo;
        bs[tid] = bb[w];
    }
#pragma unroll
    for (int i = 0; i < 16; i++) {
        int idx = tid + i * 256;
        int m = idx >> 5, j = idx & 31;
        float4 v = *(const float4*)(X + (m0 + m) * 128 + j * 4);
        *(float4*)(Xs + m * 132 + j * 4) = v;
    }
    __syncthreads();

    const int lane = tid & 31;
    const int wq = tid >> 5;
    const int g  = wq & 3;
    const int r0 = lane + 64 * (wq >> 2);

    u64 acc[2][8];
#pragma unroll
    for (int j = 0; j < 2; j++)
#pragma unroll
        for (int n = 0; n < 8; n++) acc[j][n] = 0ull;

#pragma unroll 4
    for (int k = 0; k < 128; k += 4) {
        ulonglong2 A0 = *(const ulonglong2*)(Xs + r0 * 132 + k);
        ulonglong2 A1 = *(const ulonglong2*)(Xs + (r0 + 32) * 132 + k);
#pragma unroll
        for (int n = 0; n < 8; n++) {
            ulonglong2 Bv = *(const ulonglong2*)(Ws + (g * 8 + n) * 128 + k);
            acc[0][n] = ffma2(A0.x, Bv.x, acc[0][n]);
            acc[0][n] = ffma2(A0.y, Bv.y, acc[0][n]);
            acc[1][n] = ffma2(A1.x, Bv.x, acc[1][n]);
            acc[1][n] = ffma2(A1.y, Bv.y, acc[1][n]);
        }
    }
    float bias[8];
#pragma unroll
    for (int w = 0; w < 8; w++) bias[w] = bs[g * 8 + w];
    __syncthreads();   // Xs reads done; reuse as Z staging

    float* Zs = sm;    // pitch 36
#pragma unroll
    for (int j = 0; j < 2; j++) {
        const int r = r0 + 32 * j;
        float z[8];
#pragma unroll
        for (int w = 0; w < 8; w++) {
            float2 p = *(float2*)&acc[j][w];
            z[w] = (p.x + p.y) + bias[w];
        }
        float4* dst = (float4*)(Zs + r * 36 + g * 8);
        dst[0] = make_float4(z[0], z[1], z[2], z[3]);
        dst[1] = make_float4(z[4], z[5], z[6], z[7]);
    }
    __syncthreads();
#pragma unroll
    for (int i = 0; i < 4; i++) {
        int idx = tid + i * 256;       // 0..1023 float4s
        int m = idx >> 3, q = idx & 7;
        float4 v = *(const float4*)(Zs + m * 36 + q * 4);
        *(float4*)(g_Z + (m0 + m) * 32 + q * 4) = v;
    }
}

// ---------------- eval: Z -> per-(row,gate) degree-7 poly coefficients ----------------
__global__ void __launch_bounds__(256) eval_kernel() {
    __shared__ float sPC[4][8][4], sPS[4][8][4];
    const int tid = threadIdx.x;
    if (tid < 128) ((float*)sPC)[tid] = ((const float*)g_PC)[tid];
    else if (tid < 256) ((float*)sPS)[tid - 128] = ((const float*)g_PS)[tid - 128];
    __syncthreads();

    const int g = tid & 3;
    const size_t row0 = (size_t)blockIdx.x * 128 + (size_t)(tid >> 2) * 2;
    const float off = (g == 2) ? 0.5f : 0.25f;

    float ca0[8], sa0[8], ca1[8], sa1[8];
    {
        const float4* zp0 = (const float4*)(g_Z + row0 * 32 + g * 8);
        const float4* zp1 = (const float4*)(g_Z + (row0 + 1) * 32 + g * 8);
        float4 a = zp0[0], bq = zp0[1], cq = zp1[0], d = zp1[1];
        float z0[8] = {a.x, a.y, a.z, a.w, bq.x, bq.y, bq.z, bq.w};
        float z1[8] = {cq.x, cq.y, cq.z, cq.w, d.x, d.y, d.z, d.w};
#pragma unroll
        for (int w = 0; w < 8; w++) {
            ca0[w] = __cosf(z0[w]); sa0[w] = __sinf(z0[w]);
            ca1[w] = __cosf(z1[w]); sa1[w] = __sinf(z1[w]);
        }
    }
    float ae0[4] = {off, 0.f, 0.f, 0.f}, ao0[4] = {0.f, 0.f, 0.f, 0.f};
    float ae1[4] = {off, 0.f, 0.f, 0.f}, ao1[4] = {0.f, 0.f, 0.f, 0.f};
#pragma unroll
    for (int w = 0; w < 8; w++)
#pragma unroll
        for (int jj = 0; jj < 4; jj++) {
            float pc = sPC[jj][w][g], ps = sPS[jj][w][g];
            ae0[jj] = fmaf(ca0[w], pc, ae0[jj]);
            ao0[jj] = fmaf(sa0[w], ps, ao0[jj]);
            ae1[jj] = fmaf(ca1[w], pc, ae1[jj]);
            ao1[jj] = fmaf(sa1[w], ps, ao1[jj]);
        }
    float4* op0 = (float4*)(g_A + row0 * 32 + g * 8);
    float4* op1 = (float4*)(g_A + (row0 + 1) * 32 + g * 8);
    op0[0] = make_float4(ae0[0], ao0[0], ae0[1], ao0[1]);
    op0[1] = make_float4(ae0[2], ao0[2], ae0[3], ao0[3]);
    op1[0] = make_float4(ae1[0], ao1[0], ae1[1], ao1[1]);
    op1[1] = make_float4(ae1[2], ao1[2], ae1[3], ao1[3]);
}

// ---------------- rnn: one warp per chain; compact scalar output only ----------------
__global__ void __launch_bounds__(32) rnn_kernel() {
    const int b = blockIdx.x;
    const int l = threadIdx.x;
    const int g = l & 3;               // lanes mirror lanes 0-3 (uniform lines)
    const float vm = (g == 2) ? 1.0f : 0.5f;
    const float va = (g == 2) ? 0.0f : 0.5f;

    const float* ap = g_A + (size_t)b * NG + g * 8;
    const size_t ASTR = (size_t)BATCH * NG;

    float4 p0[16], p1[16];
#pragma unroll
    for (int q = 0; q < 16; q++) {
        p0[q] = *(const float4*)(ap + (size_t)q * ASTR);
        p1[q] = *(const float4*)(ap + (size_t)q * ASTR + 4);
    }
    float s = 0.f, c = 0.f;
    for (int t0 = 0; t0 < T_STEPS; t0 += 16) {
#pragma unroll
        for (int q = 0; q < 16; q++) {
            float4 A0 = p0[q], A1 = p1[q];
            int tn = t0 + 16 + q;
            if (tn < T_STEPS) {
                p0[q] = *(const float4*)(ap + (size_t)tn * ASTR);
                p1[q] = *(const float4*)(ap + (size_t)tn * ASTR + 4);
            }
            float s2 = s * s, s4 = s2 * s2;
            float b0 = fmaf(A0.y, s, A0.x);
            float b1 = fmaf(A0.w, s, A0.z);
            float b2 = fmaf(A1.y, s, A1.x);
            float b3 = fmaf(A1.w, s, A1.z);
            float c0 = fmaf(b1, s2, b0);
            float c1 = fmaf(b3, s2, b2);
            float qv = fmaf(c1, s4, c0);
            float val = fmaf(vm, tanh_fast(qv), va);
            float f = __shfl_sync(0xffffffffu, val, 0);
            float i = __shfl_sync(0xffffffffu, val, 1);
            float u = __shfl_sync(0xffffffffu, val, 2);
            float o = __shfl_sync(0xffffffffu, val, 3);
            c = fmaf(f, c, i * u);
            s = o * tanh_fast(c);
            if (l == 0) g_S[(size_t)(t0 + q) * BATCH + b] = s;
        }
    }
    if (l == 0) g_S[(size_t)T_STEPS * BATCH + b] = c;
}

// ---------------- expand: broadcast g_S into [.,.,128]; 4 threads/row, 8 f4 each ----------------
__global__ void __launch_bounds__(256) expand_kernel(float4* __restrict__ out) {
    const size_t tid = (size_t)blockIdx.x * 256 + threadIdx.x;
    const size_t row = tid >> 2;
    const int part = (int)(tid & 3);
    const int b  = (int)(row & (BATCH - 1));
    const int tt = (int)(row >> 9);
    size_t src = row;
    if (tt == T_STEPS)     src = (size_t)(T_STEPS - 1) * BATCH + b;  // hx
    else if (tt > T_STEPS) src = (size_t)T_STEPS * BATCH + b;        // cx
    const float s = __ldg(&g_S[src]);
    const float4 v = make_float4(s, s, s, s);
    float4* dst = out + row * 32 + part * 8;
#pragma unroll
    for (int i = 0; i < 8; i++) __stcs(dst + i, v);
}

extern "C" void kernel_launch(void* const* d_in, const int* in_sizes, int n_in,
                              void* d_out, int out_size) {
    const float* X  = (const float*)d_in[0];
    const float* Wf = (const float*)d_in[1];
    const float* bf = (const float*)d_in[2];
    const float* Wi = (const float*)d_in[3];
    const float* bi = (const float*)d_in[4];
    const float* Wu = (const float*)d_in[5];
    const float* bu = (const float*)d_in[6];
    const float* Wo = (const float*)d_in[7];
    const float* bo = (const float*)d_in[8];
    float* out = (float*)d_out;

    cudaFuncSetAttribute(gemm_kernel, cudaFuncAttributeMaxDynamicSharedMemorySize,
                         GEMM_SMEM_BYTES);

    init_kernel<<<1, 32>>>(Wf, Wi, Wu, Wo);
    gemm_kernel<<<(T_STEPS * BATCH) / 128, 256, GEMM_SMEM_BYTES>>>(
        X, Wf, bf, Wi, bi, Wu, bu, Wo, bo);
    eval_kernel<<<(T_STEPS * BATCH) / 128, 256>>>();
    rnn_kernel<<<BATCH, 32>>>();
    // (T+2)*B rows * 4 threads/row / 256 = 16400 blocks
    expand_kernel<<<((T_STEPS + 2) * BATCH * 4) / 256, 256>>>((float4*)out);
}

// round 8
// speedup vs baseline: 1.5843x; 1.5843x over previous
#include <cuda_runtime.h>
#include <cstdint>
#include <math.h>

#define T_STEPS 2048
#define BATCH   512
#define DIM     128
#define HID     128
#define NG      32          // 4 gates * 8 wires
#define CH      32          // real steps per chunk
#define WU      48          // warm-up steps (0.7311^48 ~ 3e-7 contraction)
#define NCH     (T_STEPS / CH)   // 64 chunks per sample
// smem: Xs(128*132) | Ws(32*128) | bs(32) | sPC(128) | sPS(128)  (~84.6KB, 2 blocks/SM)
#define GEMM_SMEM_FLOATS (128 * 132 + 32 * 128 + 32 + 128 + 128)
#define GEMM_SMEM_BYTES  (GEMM_SMEM_FLOATS * 4)

__device__ float g_A[(size_t)T_STEPS * BATCH * NG];   // poly coeffs [row][gate][8]
__device__ float g_whsum[NG];
__device__ float g_PC[4][8][4];   // [jj][w][g] coeff of cos(z_w) in a_{2jj}
__device__ float g_PS[4][8][4];   // [jj][w][g] coeff of sin(z_w) in a_{2jj+1}

typedef unsigned long long u64;

__device__ __forceinline__ float tanh_fast(float x) {
    float r; asm("tanh.approx.f32 %0, %1;" : "=f"(r) : "f"(x)); return r;
}
__device__ __forceinline__ u64 ffma2(u64 a, u64 b, u64 c) {
    u64 d; asm("fma.rn.f32x2 %0, %1, %2, %3;" : "=l"(d) : "l"(a), "l"(b), "l"(c));
    return d;
}

// ---------------- init: whsum + Lagrange-on-Chebyshev coefficient tables ----------------
// q*sc interpolated as degree-7 poly in s on [-0.75, 0.75] (|h| <= sigmoid(1) = 0.7311).
__global__ void init_kernel(const float* __restrict__ Wf, const float* __restrict__ Wi,
                            const float* __restrict__ Wu, const float* __restrict__ Wo) {
    __shared__ double sL[8][8];
    const int n = threadIdx.x;         // 0..31
    const int g = n >> 3, w = n & 7;
    const float* W = (g == 0) ? Wf : (g == 1) ? Wi : (g == 2) ? Wu : Wo;
    float s = 0.f;
#pragma unroll
    for (int k = 0; k < 128; k++) s += W[w * 256 + 128 + k];
    g_whsum[n] = s;

    double xk[8];
#pragma unroll
    for (int k = 0; k < 8; k++) xk[k] = 0.75 * cos((2.0 * k + 1.0) * M_PI / 16.0);

    if (n < 8) {   // Lagrange basis L_n -> monomial coeffs (double)
        double cf[8];
        for (int i = 0; i < 8; i++) cf[i] = 0.0;
        cf[0] = 1.0;
        double den = 1.0;
        int deg = 0;
        for (int j = 0; j < 8; j++) {
            if (j == n) continue;
            for (int i = deg + 1; i >= 1; i--) cf[i] = cf[i - 1] - xk[j] * cf[i];
            cf[0] = -xk[j] * cf[0];
            deg++;
            den *= (xk[n] - xk[j]);
        }
        for (int j = 0; j < 8; j++) sL[n][j] = cf[j] / den;
    }
    __syncthreads();

    const double m = (g == 2) ? (1.0 / 16.0) : (1.0 / 32.0);
    for (int jj = 0; jj < 4; jj++) {
        double pc = 0.0, ps = 0.0;
        for (int k = 0; k < 8; k++) {
            double th = (double)s * xk[k];
            pc += sL[k][2 * jj]     * cos(th);
            ps += sL[k][2 * jj + 1] * sin(th);
        }
        g_PC[jj][w][g] = (float)(-m * pc);
        g_PS[jj][w][g] = (float)( m * ps);
    }
}

// ---------------- GEMM + fused eval (R4 measured-best config) ----------------
// 4m x 4n ffma2 mainloop, 2 blocks/SM; epilogue computes sincos + poly coeffs in-place.
__global__ void __launch_bounds__(256, 2) gemm_kernel(
    const float* __restrict__ X,
    const float* __restrict__ Wf, const float* __restrict__ bf,
    const float* __restrict__ Wi, const float* __restrict__ bi,
    const float* __restrict__ Wu, const float* __restrict__ bu,
    const float* __restrict__ Wo, const float* __restrict__ bo) {
    extern __shared__ float sm[];
    float* Xs  = sm;                       // [128][132]
    float* Ws  = sm + 128 * 132;           // [32][128]
    float* bs  = Ws + 32 * 128;            // [32]
    float* sPC = bs + 32;                  // [4][8][4]
    float* sPS = sPC + 128;                // [4][8][4]
    float* Zs  = sm;                       // reuse Xs region, pitch 36
    float* As  = sm + 4608;                // second half of Xs region, pitch 36
    const int tid = threadIdx.x;
    const size_t m0 = (size_t)blockIdx.x * 128;

    if (tid < 128)      sPC[tid] = ((const float*)g_PC)[tid];
    else                sPS[tid - 128] = ((const float*)g_PS)[tid - 128];

#pragma unroll
    for (int i = 0; i < 16; i++) {
        int idx = tid + i * 256;
        int n = idx >> 7, k = idx & 127;
        int g = n >> 3, w = n & 7;
        const float* W = (g == 0) ? Wf : (g == 1) ? Wi : (g == 2) ? Wu : Wo;
        Ws[n * 128 + k] = W[w * 256 + k];
    }
    if (tid < 32) {
        int g = tid >> 3, w = tid & 7;
        const float* bb = (g == 0) ? bf : (g == 1) ? bi : (g == 2) ? bu : bo;
        bs[tid] = bb[w];
    }
#pragma unroll
    for (int i = 0; i < 16; i++) {
        int idx = tid + i * 256;
        int m = idx >> 5, j = idx & 31;
        float4 v = *(const float4*)(X + (m0 + m) * 128 + j * 4);
        *(float4*)(Xs + m * 132 + j * 4) = v;
    }
    __syncthreads();

    const int lane = tid & 31;
    const int n0 = (tid >> 5) * 4;
    ulonglong2 acc[4][4];
#pragma unroll
    for (int j = 0; j < 4; j++)
#pragma unroll
        for (int i = 0; i < 4; i++) { acc[j][i].x = 0ull; acc[j][i].y = 0ull; }

#pragma unroll 4
    for (int k = 0; k < 128; k += 4) {
        ulonglong2 A[4], Bv[4];
#pragma unroll
        for (int j = 0; j < 4; j++)
            A[j] = *(const ulonglong2*)(Xs + (lane + 32 * j) * 132 + k);
#pragma unroll
        for (int i = 0; i < 4; i++)
            Bv[i] = *(const ulonglong2*)(Ws + (n0 + i) * 128 + k);
#pragma unroll
        for (int j = 0; j < 4; j++)
#pragma unroll
            for (int i = 0; i < 4; i++) {
                acc[j][i].x = ffma2(A[j].x, Bv[i].x, acc[j][i].x);
                acc[j][i].y = ffma2(A[j].y, Bv[i].y, acc[j][i].y);
            }
    }
    __syncthreads();
    // stage Z (with bias) into Zs, pitch 36
#pragma unroll
    for (int j = 0; j < 4; j++)
#pragma unroll
        for (int i = 0; i < 4; i++) {
            float2 lo = *(float2*)&acc[j][i].x;
            float2 hi = *(float2*)&acc[j][i].y;
            Zs[(lane + 32 * j) * 36 + n0 + i] = (lo.x + lo.y) + (hi.x + hi.y) + bs[n0 + i];
        }
    __syncthreads();

    // fused eval: thread -> (gate g, rows r0, r0+1)
    {
        const int g = tid & 3;
        const int r0 = (tid >> 2) * 2;
        const float off = (g == 2) ? 0.5f : 0.25f;
#pragma unroll
        for (int rr = 0; rr < 2; rr++) {
            const int r = r0 + rr;
            float ca[8], sa[8];
#pragma unroll
            for (int w = 0; w < 8; w++) {
                float z = Zs[r * 36 + g * 8 + w];
                ca[w] = __cosf(z); sa[w] = __sinf(z);
            }
            float ae[4] = {off, 0.f, 0.f, 0.f}, ao[4] = {0.f, 0.f, 0.f, 0.f};
#pragma unroll
            for (int w = 0; w < 8; w++)
#pragma unroll
                for (int jj = 0; jj < 4; jj++) {
                    ae[jj] = fmaf(ca[w], sPC[(jj * 8 + w) * 4 + g], ae[jj]);
                    ao[jj] = fmaf(sa[w], sPS[(jj * 8 + w) * 4 + g], ao[jj]);
                }
            float4* dst = (float4*)(As + r * 36 + g * 8);
            dst[0] = make_float4(ae[0], ao[0], ae[1], ao[1]);
            dst[1] = make_float4(ae[2], ao[2], ae[3], ao[3]);
        }
    }
    __syncthreads();
    // coalesced store As -> g_A (1024 float4)
#pragma unroll
    for (int i = 0; i < 4; i++) {
        int idx = tid + i * 256;
        int m = idx >> 3, q = idx & 7;
        float4 v = *(const float4*)(As + m * 36 + q * 4);
        *(float4*)(g_A + (m0 + m) * 32 + q * 4) = v;
    }
}

// ---------------- rnn_chunk: time-parallel chunks with contractive warm-up ----------------
// warp wg = ct*512 + b handles sample b, real steps [ct*32, ct*32+32), warm-starting
// WU=48 steps earlier from (s,c)=(0,0). f <= sigmoid(1)=0.7311 => truncation ~3e-7.
// Chunks 0 and 1 reach t=0 and are exact. Output rows written directly (fused expand).
__global__ void __launch_bounds__(256) rnn_chunk_kernel(float* __restrict__ out) {
    const int wg = blockIdx.x * 8 + (threadIdx.x >> 5);
    const int b  = wg & (BATCH - 1);
    const int ct = wg >> 9;            // 0..NCH-1
    const int l  = threadIdx.x & 31;
    const int g  = l & 3;
    const float vm = (g == 2) ? 1.0f : 0.5f;
    const float va = (g == 2) ? 0.0f : 0.5f;

    const int t0 = ct * CH;
    const int tw = (t0 >= WU) ? (t0 - WU) : 0;
    const int total = t0 + CH - tw;    // 32, 64, or 80
    const int skip  = t0 - tw;         // warm steps

    const float* ap = g_A + ((size_t)tw * BATCH + b) * NG + g * 8;
    const size_t ASTR = (size_t)BATCH * NG;

    float4 p0[4], p1[4];
#pragma unroll
    for (int q = 0; q < 4; q++) {
        p0[q] = *(const float4*)(ap + (size_t)q * ASTR);
        p1[q] = *(const float4*)(ap + (size_t)q * ASTR + 4);
    }
    float s = 0.f, c = 0.f;
    for (int i0 = 0; i0 < total; i0 += 4) {
#pragma unroll
        for (int q = 0; q < 4; q++) {
            float4 A0 = p0[q], A1 = p1[q];
            int nx = i0 + 4 + q;
            if (nx < total) {
                p0[q] = *(const float4*)(ap + (size_t)nx * ASTR);
                p1[q] = *(const float4*)(ap + (size_t)nx * ASTR + 4);
            }
            // Estrin degree-7: coeffs a0..a7 = (A0.x..A0.w, A1.x..A1.w)
            float s2 = s * s, s4 = s2 * s2;
            float b0 = fmaf(A0.y, s, A0.x);
            float b1 = fmaf(A0.w, s, A0.z);
            float b2 = fmaf(A1.y, s, A1.x);
            float b3 = fmaf(A1.w, s, A1.z);
            float c0v = fmaf(b1, s2, b0);
            float c1v = fmaf(b3, s2, b2);
            float qv = fmaf(c1v, s4, c0v);
            float val = fmaf(vm, tanh_fast(qv), va);
            float f = __shfl_sync(0xffffffffu, val, 0);
            float i = __shfl_sync(0xffffffffu, val, 1);
            float u = __shfl_sync(0xffffffffu, val, 2);
            float o = __shfl_sync(0xffffffffu, val, 3);
            c = fmaf(f, c, i * u);
            s = o * tanh_fast(c);
            int it = i0 + q;
            if (it >= skip) {          // real step: store broadcast h row
                const size_t t = (size_t)(tw + it);
                float4 v = make_float4(s, s, s, s);
                *(float4*)(out + (t * BATCH + b) * HID + l * 4) = v;
            }
        }
    }
    if (ct == NCH - 1) {               // hx = h[T-1], cx = final c
        float4 vs = make_float4(s, s, s, s);
        *(float4*)(out + ((size_t)T_STEPS * BATCH + b) * HID + l * 4) = vs;
        float4 vc = make_float4(c, c, c, c);
        *(float4*)(out + ((size_t)T_STEPS * BATCH + BATCH + b) * HID + l * 4) = vc;
    }
}

extern "C" void kernel_launch(void* const* d_in, const int* in_sizes, int n_in,
                              void* d_out, int out_size) {
    const float* X  = (const float*)d_in[0];
    const float* Wf = (const float*)d_in[1];
    const float* bf = (const float*)d_in[2];
    const float* Wi = (const float*)d_in[3];
    const float* bi = (const float*)d_in[4];
    const float* Wu = (const float*)d_in[5];
    const float* bu = (const float*)d_in[6];
    const float* Wo = (const float*)d_in[7];
    const float* bo = (const float*)d_in[8];
    float* out = (float*)d_out;

    cudaFuncSetAttribute(gemm_kernel, cudaFuncAttributeMaxDynamicSharedMemorySize,
                         GEMM_SMEM_BYTES);

    init_kernel<<<1, 32>>>(Wf, Wi, Wu, Wo);
    gemm_kernel<<<(T_STEPS * BATCH) / 128, 256, GEMM_SMEM_BYTES>>>(
        X, Wf, bf, Wi, bi, Wu, bu, Wo, bo);
    // 512 samples * 64 chunks / 8 warps per block = 4096 blocks
    rnn_chunk_kernel<<<(BATCH * NCH) / 8, 256>>>(out);
}

// round 9
// speedup vs baseline: 1.6588x; 1.0470x over previous
#include <cuda_runtime.h>
#include <cstdint>
#include <math.h>

#define T_STEPS 2048
#define BATCH   512
#define DIM     128
#define HID     128
#define NG      32          // 4 gates * 8 wires
#define CH      32          // real steps per chunk
#define WU      48          // warm-up steps (0.7311^48 ~ 3e-7 contraction)
#define NCH     (T_STEPS / CH)   // 64 chunks per sample
// smem: Xs(128*132) | Ws(32*128) | bs(32) | sPC(128) | sPS(128)  (~84.6KB, 2 blocks/SM)
#define GEMM_SMEM_FLOATS (128 * 132 + 32 * 128 + 32 + 128 + 128)
#define GEMM_SMEM_BYTES  (GEMM_SMEM_FLOATS * 4)

__device__ float g_A[(size_t)T_STEPS * BATCH * NG];   // poly coeffs [row][gate][8]
__device__ float g_PC[4][8][4];   // [jj][w][g] coeff of cos(z_w) in a_{2jj}
__device__ float g_PS[4][8][4];   // [jj][w][g] coeff of sin(z_w) in a_{2jj+1}

typedef unsigned long long u64;

__device__ __forceinline__ float tanh_fast(float x) {
    float r; asm("tanh.approx.f32 %0, %1;" : "=f"(r) : "f"(x)); return r;
}
__device__ __forceinline__ u64 ffma2(u64 a, u64 b, u64 c) {
    u64 d; asm("fma.rn.f32x2 %0, %1, %2, %3;" : "=l"(d) : "l"(a), "l"(b), "l"(c));
    return d;
}

// ---------------- init: whsum + Lagrange-on-Chebyshev coefficient tables ----------------
// Parallelized: 1 block x 1024 threads. Phase 1: warp n butterfly-reduces whsum_n.
// Phase 2: threads 0-7 build Lagrange monomial coeffs (double, cheap). Phase 3:
// 128 threads, one per (n, jj), each does only 8 double cos + 8 double sin.
__global__ void __launch_bounds__(1024) init_kernel(
        const float* __restrict__ Wf, const float* __restrict__ Wi,
        const float* __restrict__ Wu, const float* __restrict__ Wo) {
    __shared__ float  swh[32];
    __shared__ double sL[8][8];        // [node k][monomial j]
    const int tid = threadIdx.x;
    const int warp = tid >> 5, lane = tid & 31;

    // Phase 1: whsum (row sums of the H-part), one warp per (gate, wire)
    {
        const int g = warp >> 3, w = warp & 7;
        const float* W = (g == 0) ? Wf : (g == 1) ? Wi : (g == 2) ? Wu : Wo;
        const float4 v = *(const float4*)(W + w * (DIM + HID) + DIM + lane * 4);
        float s = (v.x + v.y) + (v.z + v.w);
        s += __shfl_xor_sync(0xffffffffu, s, 1);
        s += __shfl_xor_sync(0xffffffffu, s, 2);
        s += __shfl_xor_sync(0xffffffffu, s, 4);
        s += __shfl_xor_sync(0xffffffffu, s, 8);
        s += __shfl_xor_sync(0xffffffffu, s, 16);
        if (lane == 0) swh[warp] = s;
    }

    // Phase 2: Lagrange basis L_n -> monomial coeffs (threads 0..7)
    if (tid < 8) {
        const int n = tid;
        double xk[8];
#pragma unroll
        for (int k = 0; k < 8; k++) xk[k] = 0.75 * cos((2.0 * k + 1.0) * M_PI / 16.0);
        double cf[8];
        for (int i = 0; i < 8; i++) cf[i] = 0.0;
        cf[0] = 1.0;
        double den = 1.0;
        int deg = 0;
        for (int j = 0; j < 8; j++) {
            if (j == n) continue;
            for (int i = deg + 1; i >= 1; i--) cf[i] = cf[i - 1] - xk[j] * cf[i];
            cf[0] = -xk[j] * cf[0];
            deg++;
            den *= (xk[n] - xk[j]);
        }
        for (int j = 0; j < 8; j++) sL[n][j] = cf[j] / den;
    }
    __syncthreads();

    // Phase 3: one thread per (n, jj): 8 double cos + 8 double sin
    if (tid < 128) {
        const int n  = tid >> 2;       // 0..31
        const int jj = tid & 3;
        const int g = n >> 3, w = n & 7;
        const double s = (double)swh[n];
        const double m = (g == 2) ? (1.0 / 16.0) : (1.0 / 32.0);
        double xk[8];
#pragma unroll
        for (int k = 0; k < 8; k++) xk[k] = 0.75 * cos((2.0 * k + 1.0) * M_PI / 16.0);
        double pc = 0.0, ps = 0.0;
#pragma unroll
        for (int k = 0; k < 8; k++) {
            double th = s * xk[k];
            pc += sL[k][2 * jj]     * cos(th);
            ps += sL[k][2 * jj + 1] * sin(th);
        }
        g_PC[jj][w][g] = (float)(-m * pc);
        g_PS[jj][w][g] = (float)( m * ps);
    }
}

// ---------------- GEMM + fused eval (R4/R8 measured-best config, UNCHANGED) ----------------
__global__ void __launch_bounds__(256, 2) gemm_kernel(
    const float* __restrict__ X,
    const float* __restrict__ Wf, const float* __restrict__ bf,
    const float* __restrict__ Wi, const float* __restrict__ bi,
    const float* __restrict__ Wu, const float* __restrict__ bu,
    const float* __restrict__ Wo, const float* __restrict__ bo) {
    extern __shared__ float sm[];
    float* Xs  = sm;                       // [128][132]
    float* Ws  = sm + 128 * 132;           // [32][128]
    float* bs  = Ws + 32 * 128;            // [32]
    float* sPC = bs + 32;                  // [4][8][4]
    float* sPS = sPC + 128;                // [4][8][4]
    float* Zs  = sm;                       // reuse Xs region, pitch 36
    float* As  = sm + 4608;                // second half of Xs region, pitch 36
    const int tid = threadIdx.x;
    const size_t m0 = (size_t)blockIdx.x * 128;

    if (tid < 128)      sPC[tid] = ((const float*)g_PC)[tid];
    else                sPS[tid - 128] = ((const float*)g_PS)[tid - 128];

#pragma unroll
    for (int i = 0; i < 16; i++) {
        int idx = tid + i * 256;
        int n = idx >> 7, k = idx & 127;
        int g = n >> 3, w = n & 7;
        const float* W = (g == 0) ? Wf : (g == 1) ? Wi : (g == 2) ? Wu : Wo;
        Ws[n * 128 + k] = W[w * 256 + k];
    }
    if (tid < 32) {
        int g = tid >> 3, w = tid & 7;
        const float* bb = (g == 0) ? bf : (g == 1) ? bi : (g == 2) ? bu : bo;
        bs[tid] = bb[w];
    }
#pragma unroll
    for (int i = 0; i < 16; i++) {
        int idx = tid + i * 256;
        int m = idx >> 5, j = idx & 31;
        float4 v = *(const float4*)(X + (m0 + m) * 128 + j * 4);
        *(float4*)(Xs + m * 132 + j * 4) = v;
    }
    __syncthreads();

    const int lane = tid & 31;
    const int n0 = (tid >> 5) * 4;
    ulonglong2 acc[4][4];
#pragma unroll
    for (int j = 0; j < 4; j++)
#pragma unroll
        for (int i = 0; i < 4; i++) { acc[j][i].x = 0ull; acc[j][i].y = 0ull; }

#pragma unroll 4
    for (int k = 0; k < 128; k += 4) {
        ulonglong2 A[4], Bv[4];
#pragma unroll
        for (int j = 0; j < 4; j++)
            A[j] = *(const ulonglong2*)(Xs + (lane + 32 * j) * 132 + k);
#pragma unroll
        for (int i = 0; i < 4; i++)
            Bv[i] = *(const ulonglong2*)(Ws + (n0 + i) * 128 + k);
#pragma unroll
        for (int j = 0; j < 4; j++)
#pragma unroll
            for (int i = 0; i < 4; i++) {
                acc[j][i].x = ffma2(A[j].x, Bv[i].x, acc[j][i].x);
                acc[j][i].y = ffma2(A[j].y, Bv[i].y, acc[j][i].y);
            }
    }
    __syncthreads();
    // stage Z (with bias) into Zs, pitch 36
#pragma unroll
    for (int j = 0; j < 4; j++)
#pragma unroll
        for (int i = 0; i < 4; i++) {
            float2 lo = *(float2*)&acc[j][i].x;
            float2 hi = *(float2*)&acc[j][i].y;
            Zs[(lane + 32 * j) * 36 + n0 + i] = (lo.x + lo.y) + (hi.x + hi.y) + bs[n0 + i];
        }
    __syncthreads();

    // fused eval: thread -> (gate g, rows r0, r0+1)
    {
        const int g = tid & 3;
        const int r0 = (tid >> 2) * 2;
        const float off = (g == 2) ? 0.5f : 0.25f;
#pragma unroll
        for (int rr = 0; rr < 2; rr++) {
            const int r = r0 + rr;
            float ca[8], sa[8];
#pragma unroll
            for (int w = 0; w < 8; w++) {
                float z = Zs[r * 36 + g * 8 + w];
                ca[w] = __cosf(z); sa[w] = __sinf(z);
            }
            float ae[4] = {off, 0.f, 0.f, 0.f}, ao[4] = {0.f, 0.f, 0.f, 0.f};
#pragma unroll
            for (int w = 0; w < 8; w++)
#pragma unroll
                for (int jj = 0; jj < 4; jj++) {
                    ae[jj] = fmaf(ca[w], sPC[(jj * 8 + w) * 4 + g], ae[jj]);
                    ao[jj] = fmaf(sa[w], sPS[(jj * 8 + w) * 4 + g], ao[jj]);
                }
            float4* dst = (float4*)(As + r * 36 + g * 8);
            dst[0] = make_float4(ae[0], ao[0], ae[1], ao[1]);
            dst[1] = make_float4(ae[2], ao[2], ae[3], ao[3]);
        }
    }
    __syncthreads();
    // coalesced store As -> g_A (1024 float4)
#pragma unroll
    for (int i = 0; i < 4; i++) {
        int idx = tid + i * 256;
        int m = idx >> 3, q = idx & 7;
        float4 v = *(const float4*)(As + m * 36 + q * 4);
        *(float4*)(g_A + (m0 + m) * 32 + q * 4) = v;
    }
}

// ---------------- rnn_chunk: time-parallel chunks with contractive warm-up (UNCHANGED) ----------------
__global__ void __launch_bounds__(256) rnn_chunk_kernel(float* __restrict__ out) {
    const int wg = blockIdx.x * 8 + (threadIdx.x >> 5);
    const int b  = wg & (BATCH - 1);
    const int ct = wg >> 9;            // 0..NCH-1
    const int l  = threadIdx.x & 31;
    const int g  = l & 3;
    const float vm = (g == 2) ? 1.0f : 0.5f;
    const float va = (g == 2) ? 0.0f : 0.5f;

    const int t0 = ct * CH;
    const int tw = (t0 >= WU) ? (t0 - WU) : 0;
    const int total = t0 + CH - tw;    // 32, 64, or 80
    const int skip  = t0 - tw;         // warm steps

    const float* ap = g_A + ((size_t)tw * BATCH + b) * NG + g * 8;
    const size_t ASTR = (size_t)BATCH * NG;

    float4 p0[4], p1[4];
#pragma unroll
    for (int q = 0; q < 4; q++) {
        p0[q] = *(const float4*)(ap + (size_t)q * ASTR);
        p1[q] = *(const float4*)(ap + (size_t)q * ASTR + 4);
    }
    float s = 0.f, c = 0.f;
    for (int i0 = 0; i0 < total; i0 += 4) {
#pragma unroll
        for (int q = 0; q < 4; q++) {
            float4 A0 = p0[q], A1 = p1[q];
            int nx = i0 + 4 + q;
            if (nx < total) {
                p0[q] = *(const float4*)(ap + (size_t)nx * ASTR);
                p1[q] = *(const float4*)(ap + (size_t)nx * ASTR + 4);
            }
            float s2 = s * s, s4 = s2 * s2;
            float b0 = fmaf(A0.y, s, A0.x);
            float b1 = fmaf(A0.w, s, A0.z);
            float b2 = fmaf(A1.y, s, A1.x);
            float b3 = fmaf(A1.w, s, A1.z);
            float c0v = fmaf(b1, s2, b0);
            float c1v = fmaf(b3, s2, b2);
            float qv = fmaf(c1v, s4, c0v);
            float val = fmaf(vm, tanh_fast(qv), va);
            float f = __shfl_sync(0xffffffffu, val, 0);
            float i = __shfl_sync(0xffffffffu, val, 1);
            float u = __shfl_sync(0xffffffffu, val, 2);
            float o = __shfl_sync(0xffffffffu, val, 3);
            c = fmaf(f, c, i * u);
            s = o * tanh_fast(c);
            int it = i0 + q;
            if (it >= skip) {
                const size_t t = (size_t)(tw + it);
                float4 v = make_float4(s, s, s, s);
                *(float4*)(out + (t * BATCH + b) * HID + l * 4) = v;
            }
        }
    }
    if (ct == NCH - 1) {
        float4 vs = make_float4(s, s, s, s);
        *(float4*)(out + ((size_t)T_STEPS * BATCH + b) * HID + l * 4) = vs;
        float4 vc = make_float4(c, c, c, c);
        *(float4*)(out + ((size_t)T_STEPS * BATCH + BATCH + b) * HID + l * 4) = vc;
    }
}

extern "C" void kernel_launch(void* const* d_in, const int* in_sizes, int n_in,
                              void* d_out, int out_size) {
    const float* X  = (const float*)d_in[0];
    const float* Wf = (const float*)d_in[1];
    const float* bf = (const float*)d_in[2];
    const float* Wi = (const float*)d_in[3];
    const float* bi = (const float*)d_in[4];
    const float* Wu = (const float*)d_in[5];
    const float* bu = (const float*)d_in[6];
    const float* Wo = (const float*)d_in[7];
    const float* bo = (const float*)d_in[8];
    float* out = (float*)d_out;

    cudaFuncSetAttribute(gemm_kernel, cudaFuncAttributeMaxDynamicSharedMemorySize,
                         GEMM_SMEM_BYTES);

    init_kernel<<<1, 1024>>>(Wf, Wi, Wu, Wo);
    gemm_kernel<<<(T_STEPS * BATCH) / 128, 256, GEMM_SMEM_BYTES>>>(
        X, Wf, bf, Wi, bi, Wu, bu, Wo, bo);
    rnn_chunk_kernel<<<(BATCH * NCH) / 8, 256>>>(out);
}

// round 10
// speedup vs baseline: 1.7634x; 1.0630x over previous
#include <cuda_runtime.h>
#include <cstdint>
#include <math.h>

#define T_STEPS 2048
#define BATCH   512
#define DIM     128
#define HID     128
#define NG      32          // 4 gates * 8 wires
#define CH      64          // real steps per chunk
#define WU      48          // warm-up steps (0.7311^48 ~ 3e-7 contraction)
#define NCH     (T_STEPS / CH)   // 32 chunks per sample
// smem: Xs(128*132) | Ws(32*128) | bs(32) | sPC(128) | sPS(128)  (~84.6KB, 2 blocks/SM)
#define GEMM_SMEM_FLOATS (128 * 132 + 32 * 128 + 32 + 128 + 128)
#define GEMM_SMEM_BYTES  (GEMM_SMEM_FLOATS * 4)

__device__ float g_A[(size_t)T_STEPS * BATCH * NG];   // poly coeffs [row][gate][8]
__device__ float g_PC[4][8][4];   // [jj][w][g] coeff of cos(z_w) in a_{2jj}
__device__ float g_PS[4][8][4];   // [jj][w][g] coeff of sin(z_w) in a_{2jj+1}

typedef unsigned long long u64;

// Chebyshev nodes xk = 0.75*cos((2k+1)pi/16), hardcoded (no runtime fp64 trig)
__device__ __constant__ double c_xk[8] = {
     0.73558896030242283695,  0.62360220922690892768,
     0.41667767476470166891,  0.14631774151209620177,
    -0.14631774151209620177, -0.41667767476470166891,
    -0.62360220922690892768, -0.73558896030242283695
};

__device__ __forceinline__ float tanh_fast(float x) {
    float r; asm("tanh.approx.f32 %0, %1;" : "=f"(r) : "f"(x)); return r;
}
__device__ __forceinline__ u64 ffma2(u64 a, u64 b, u64 c) {
    u64 d; asm("fma.rn.f32x2 %0, %1, %2, %3;" : "=l"(d) : "l"(a), "l"(b), "l"(c));
    return d;
}

// ---------------- init: whsum + Lagrange-on-Chebyshev coefficient tables ----------------
// No runtime fp64 trig: nodes are constants; phase-3 trig uses float sinf/cosf
// (~1e-7 error, well under the 2.5e-6 interpolation budget), double accumulation.
__global__ void __launch_bounds__(1024) init_kernel(
        const float* __restrict__ Wf, const float* __restrict__ Wi,
        const float* __restrict__ Wu, const float* __restrict__ Wo) {
    __shared__ float  swh[32];
    __shared__ double sL[8][8];        // [node k][monomial j]
    const int tid = threadIdx.x;
    const int warp = tid >> 5, lane = tid & 31;

    // Phase 1: whsum (row sums of the H-part), one warp per (gate, wire)
    {
        const int g = warp >> 3, w = warp & 7;
        const float* W = (g == 0) ? Wf : (g == 1) ? Wi : (g == 2) ? Wu : Wo;
        const float4 v = *(const float4*)(W + w * (DIM + HID) + DIM + lane * 4);
        float s = (v.x + v.y) + (v.z + v.w);
        s += __shfl_xor_sync(0xffffffffu, s, 1);
        s += __shfl_xor_sync(0xffffffffu, s, 2);
        s += __shfl_xor_sync(0xffffffffu, s, 4);
        s += __shfl_xor_sync(0xffffffffu, s, 8);
        s += __shfl_xor_sync(0xffffffffu, s, 16);
        if (lane == 0) swh[warp] = s;
    }

    // Phase 2: Lagrange basis L_n -> monomial coeffs (threads 0..7, fp64 FMA only)
    if (tid < 8) {
        const int n = tid;
        double cf[8];
        for (int i = 0; i < 8; i++) cf[i] = 0.0;
        cf[0] = 1.0;
        double den = 1.0;
        int deg = 0;
        for (int j = 0; j < 8; j++) {
            if (j == n) continue;
            for (int i = deg + 1; i >= 1; i--) cf[i] = cf[i - 1] - c_xk[j] * cf[i];
            cf[0] = -c_xk[j] * cf[0];
            deg++;
            den *= (c_xk[n] - c_xk[j]);
        }
        for (int j = 0; j < 8; j++) sL[n][j] = cf[j] / den;
    }
    __syncthreads();

    // Phase 3: one thread per (n, jj): 8 float cos + 8 float sin, double accumulate
    if (tid < 128) {
        const int n  = tid >> 2;       // 0..31
        const int jj = tid & 3;
        const int g = n >> 3, w = n & 7;
        const double s = (double)swh[n];
        const double m = (g == 2) ? (1.0 / 16.0) : (1.0 / 32.0);
        double pc = 0.0, ps = 0.0;
#pragma unroll
        for (int k = 0; k < 8; k++) {
            float th = (float)(s * c_xk[k]);
            pc += sL[k][2 * jj]     * (double)cosf(th);
            ps += sL[k][2 * jj + 1] * (double)sinf(th);
        }
        g_PC[jj][w][g] = (float)(-m * pc);
        g_PS[jj][w][g] = (float)( m * ps);
    }
}

// ---------------- GEMM + fused eval (R4/R8 measured-best config, UNCHANGED) ----------------
__global__ void __launch_bounds__(256, 2) gemm_kernel(
    const float* __restrict__ X,
    const float* __restrict__ Wf, const float* __restrict__ bf,
    const float* __restrict__ Wi, const float* __restrict__ bi,
    const float* __restrict__ Wu, const float* __restrict__ bu,
    const float* __restrict__ Wo, const float* __restrict__ bo) {
    extern __shared__ float sm[];
    float* Xs  = sm;                       // [128][132]
    float* Ws  = sm + 128 * 132;           // [32][128]
    float* bs  = Ws + 32 * 128;            // [32]
    float* sPC = bs + 32;                  // [4][8][4]
    float* sPS = sPC + 128;                // [4][8][4]
    float* Zs  = sm;                       // reuse Xs region, pitch 36
    float* As  = sm + 4608;                // second half of Xs region, pitch 36
    const int tid = threadIdx.x;
    const size_t m0 = (size_t)blockIdx.x * 128;

    if (tid < 128)      sPC[tid] = ((const float*)g_PC)[tid];
    else                sPS[tid - 128] = ((const float*)g_PS)[tid - 128];

#pragma unroll
    for (int i = 0; i < 16; i++) {
        int idx = tid + i * 256;
        int n = idx >> 7, k = idx & 127;
        int g = n >> 3, w = n & 7;
        const float* W = (g == 0) ? Wf : (g == 1) ? Wi : (g == 2) ? Wu : Wo;
        Ws[n * 128 + k] = W[w * 256 + k];
    }
    if (tid < 32) {
        int g = tid >> 3, w = tid & 7;
        const float* bb = (g == 0) ? bf : (g == 1) ? bi : (g == 2) ? bu : bo;
        bs[tid] = bb[w];
    }
#pragma unroll
    for (int i = 0; i < 16; i++) {
        int idx = tid + i * 256;
        int m = idx >> 5, j = idx & 31;
        float4 v = *(const float4*)(X + (m0 + m) * 128 + j * 4);
        *(float4*)(Xs + m * 132 + j * 4) = v;
    }
    __syncthreads();

    const int lane = tid & 31;
    const int n0 = (tid >> 5) * 4;
    ulonglong2 acc[4][4];
#pragma unroll
    for (int j = 0; j < 4; j++)
#pragma unroll
        for (int i = 0; i < 4; i++) { acc[j][i].x = 0ull; acc[j][i].y = 0ull; }

#pragma unroll 4
    for (int k = 0; k < 128; k += 4) {
        ulonglong2 A[4], Bv[4];
#pragma unroll
        for (int j = 0; j < 4; j++)
            A[j] = *(const ulonglong2*)(Xs + (lane + 32 * j) * 132 + k);
#pragma unroll
        for (int i = 0; i < 4; i++)
            Bv[i] = *(const ulonglong2*)(Ws + (n0 + i) * 128 + k);
#pragma unroll
        for (int j = 0; j < 4; j++)
#pragma unroll
            for (int i = 0; i < 4; i++) {
                acc[j][i].x = ffma2(A[j].x, Bv[i].x, acc[j][i].x);
                acc[j][i].y = ffma2(A[j].y, Bv[i].y, acc[j][i].y);
            }
    }
    __syncthreads();
    // stage Z (with bias) into Zs, pitch 36
#pragma unroll
    for (int j = 0; j < 4; j++)
#pragma unroll
        for (int i = 0; i < 4; i++) {
            float2 lo = *(float2*)&acc[j][i].x;
            float2 hi = *(float2*)&acc[j][i].y;
            Zs[(lane + 32 * j) * 36 + n0 + i] = (lo.x + lo.y) + (hi.x + hi.y) + bs[n0 + i];
        }
    __syncthreads();

    // fused eval: thread -> (gate g, rows r0, r0+1)
    {
        const int g = tid & 3;
        const int r0 = (tid >> 2) * 2;
        const float off = (g == 2) ? 0.5f : 0.25f;
#pragma unroll
        for (int rr = 0; rr < 2; rr++) {
            const int r = r0 + rr;
            float ca[8], sa[8];
#pragma unroll
            for (int w = 0; w < 8; w++) {
                float z = Zs[r * 36 + g * 8 + w];
                ca[w] = __cosf(z); sa[w] = __sinf(z);
            }
            float ae[4] = {off, 0.f, 0.f, 0.f}, ao[4] = {0.f, 0.f, 0.f, 0.f};
#pragma unroll
            for (int w = 0; w < 8; w++)
#pragma unroll
                for (int jj = 0; jj < 4; jj++) {
                    ae[jj] = fmaf(ca[w], sPC[(jj * 8 + w) * 4 + g], ae[jj]);
                    ao[jj] = fmaf(sa[w], sPS[(jj * 8 + w) * 4 + g], ao[jj]);
                }
            float4* dst = (float4*)(As + r * 36 + g * 8);
            dst[0] = make_float4(ae[0], ao[0], ae[1], ao[1]);
            dst[1] = make_float4(ae[2], ao[2], ae[3], ao[3]);
        }
    }
    __syncthreads();
    // coalesced store As -> g_A (1024 float4)
#pragma unroll
    for (int i = 0; i < 4; i++) {
        int idx = tid + i * 256;
        int m = idx >> 3, q = idx & 7;
        float4 v = *(const float4*)(As + m * 36 + q * 4);
        *(float4*)(g_A + (m0 + m) * 32 + q * 4) = v;
    }
}

// ---------------- rnn_chunk: time-parallel chunks, CH=64 (less warm-up overhead) ----------------
__global__ void __launch_bounds__(256) rnn_chunk_kernel(float* __restrict__ out) {
    const int wg = blockIdx.x * 8 + (threadIdx.x >> 5);
    const int b  = wg & (BATCH - 1);
    const int ct = wg >> 9;            // 0..NCH-1
    const int l  = threadIdx.x & 31;
    const int g  = l & 3;
    const float vm = (g == 2) ? 1.0f : 0.5f;
    const float va = (g == 2) ? 0.0f : 0.5f;

    const int t0 = ct * CH;
    const int tw = (t0 >= WU) ? (t0 - WU) : 0;
    const int total = t0 + CH - tw;    // 64 or 112
    const int skip  = t0 - tw;         // warm steps (0 or 48)

    const float* ap = g_A + ((size_t)tw * BATCH + b) * NG + g * 8;
    const size_t ASTR = (size_t)BATCH * NG;

    float4 p0[4], p1[4];
#pragma unroll
    for (int q = 0; q < 4; q++) {
        p0[q] = *(const float4*)(ap + (size_t)q * ASTR);
        p1[q] = *(const float4*)(ap + (size_t)q * ASTR + 4);
    }
    float s = 0.f, c = 0.f;
    for (int i0 = 0; i0 < total; i0 += 4) {
#pragma unroll
        for (int q = 0; q < 4; q++) {
            float4 A0 = p0[q], A1 = p1[q];
            int nx = i0 + 4 + q;
            if (nx < total) {
                p0[q] = *(const float4*)(ap + (size_t)nx * ASTR);
                p1[q] = *(const float4*)(ap + (size_t)nx * ASTR + 4);
            }
            // Estrin degree-7: coeffs a0..a7 = (A0.x..A0.w, A1.x..A1.w)
            float s2 = s * s, s4 = s2 * s2;
            float b0 = fmaf(A0.y, s, A0.x);
            float b1 = fmaf(A0.w, s, A0.z);
            float b2 = fmaf(A1.y, s, A1.x);
            float b3 = fmaf(A1.w, s, A1.z);
            float c0v = fmaf(b1, s2, b0);
            float c1v = fmaf(b3, s2, b2);
            float qv = fmaf(c1v, s4, c0v);
            float val = fmaf(vm, tanh_fast(qv), va);
            float f = __shfl_sync(0xffffffffu, val, 0);
            float i = __shfl_sync(0xffffffffu, val, 1);
            float u = __shfl_sync(0xffffffffu, val, 2);
            float o = __shfl_sync(0xffffffffu, val, 3);
            c = fmaf(f, c, i * u);
            s = o * tanh_fast(c);
            int it = i0 + q;
            if (it >= skip) {          // real step: store broadcast h row
                const size_t t = (size_t)(tw + it);
                float4 v = make_float4(s, s, s, s);
                *(float4*)(out + (t * BATCH + b) * HID + l * 4) = v;
            }
        }
    }
    if (ct == NCH - 1) {               // hx = h[T-1], cx = final c
        float4 vs = make_float4(s, s, s, s);
        *(float4*)(out + ((size_t)T_STEPS * BATCH + b) * HID + l * 4) = vs;
        float4 vc = make_float4(c, c, c, c);
        *(float4*)(out + ((size_t)T_STEPS * BATCH + BATCH + b) * HID + l * 4) = vc;
    }
}

extern "C" void kernel_launch(void* const* d_in, const int* in_sizes, int n_in,
                              void* d_out, int out_size) {
    const float* X  = (const float*)d_in[0];
    const float* Wf = (const float*)d_in[1];
    const float* bf = (const float*)d_in[2];
    const float* Wi = (const float*)d_in[3];
    const float* bi = (const float*)d_in[4];
    const float* Wu = (const float*)d_in[5];
    const float* bu = (const float*)d_in[6];
    const float* Wo = (const float*)d_in[7];
    const float* bo = (const float*)d_in[8];
    float* out = (float*)d_out;

    cudaFuncSetAttribute(gemm_kernel, cudaFuncAttributeMaxDynamicSharedMemorySize,
                         GEMM_SMEM_BYTES);

    init_kernel<<<1, 1024>>>(Wf, Wi, Wu, Wo);
    gemm_kernel<<<(T_STEPS * BATCH) / 128, 256, GEMM_SMEM_BYTES>>>(
        X, Wf, bf, Wi, bi, Wu, bu, Wo, bo);
    // 512 samples * 32 chunks / 8 warps per block = 2048 blocks
    rnn_chunk_kernel<<<(BATCH * NCH) / 8, 256>>>(out);
}